// round 13
// baseline (speedup 1.0000x reference)
#include <cuda_runtime.h>
#include <cuda_bf16.h>
#include <math.h>
#include <stdint.h>

// ---------------------------------------------------------------------------
// Swin block: B=32, H=W=128, C=128, WS=2, SS=1, NH=8, HD=16
// 3 fused kernels. GEMMs: mma.sync plain bf16 1-pass, k64 weight chunks.
// R13: barrier-diet — qkv 5-buffer W (3 barriers), attnproj 1 barrier,
// attention 16B loads. mlp unchanged from R12.
// ---------------------------------------------------------------------------

#define TOK   524288

typedef __nv_bfloat16 bf16;

__device__ bf16  g_qkv[(size_t)TOK * 384];   // bf16 qkv (q pre-scaled)
__device__ float g_h2 [(size_t)TOK * 128];
// weights transposed to [N,K] bf16
__device__ bf16  g_wq[384 * 128];
__device__ bf16  g_wp[128 * 128];
__device__ bf16  g_w1[256 * 128];
__device__ bf16  g_w2[128 * 256];

// ---------------------------------------------------------------------------
__device__ __forceinline__ uint32_t smem_u32(const void* p) {
    uint32_t a;
    asm("{ .reg .u64 t; cvta.to.shared.u64 t, %1; cvt.u32.u64 %0, t; }"
        : "=r"(a) : "l"(p));
    return a;
}

#define SWZ128(o) ((o) ^ (((o) >> 3) & 0x70))

#define CP_ASYNC16(dst, src) \
    asm volatile("cp.async.cg.shared.global [%0], [%1], 16;" \
                 :: "r"(dst), "l"(src) : "memory")
#define CP_COMMIT()  asm volatile("cp.async.commit_group;" ::: "memory")
#define CP_WAIT(n)   asm volatile("cp.async.wait_group %0;" :: "n"(n) : "memory")

__device__ __forceinline__ void ldsm4(uint32_t r[4], uint32_t addr) {
    asm volatile("ldmatrix.sync.aligned.m8n8.x4.shared.b16 {%0,%1,%2,%3}, [%4];"
                 : "=r"(r[0]), "=r"(r[1]), "=r"(r[2]), "=r"(r[3]) : "r"(addr));
}

__device__ __forceinline__ void mma_bf16(float4& d, const uint32_t a[4],
                                         const uint32_t b[2]) {
    asm volatile(
        "mma.sync.aligned.m16n8k16.row.col.f32.bf16.bf16.f32 "
        "{%0,%1,%2,%3}, {%4,%5,%6,%7}, {%8,%9}, {%0,%1,%2,%3};"
        : "+f"(d.x), "+f"(d.y), "+f"(d.z), "+f"(d.w)
        : "r"(a[0]), "r"(a[1]), "r"(a[2]), "r"(a[3]), "r"(b[0]), "r"(b[1]));
}

__device__ __forceinline__ int orig_of(int r) {
    int win = r >> 2, s = r & 3;
    int b  = win >> 12;
    int w  = win & 4095;
    int wh = w >> 6, ww = w & 63;
    int ii = ((wh << 1) + (s >> 1) + 1) & 127;
    int jj = ((ww << 1) + (s & 1) + 1) & 127;
    return (b << 14) + (ii << 7) + jj;
}

__device__ __forceinline__ uint32_t pk2(float a, float b) {
    __nv_bfloat162 t = __floats2bfloat162_rn(a, b);
    return *(uint32_t*)&t;
}
// 8 consecutive bf16 -> 8 floats (16B load)
struct f8 { float v[8]; };
__device__ __forceinline__ f8 ld8bf(const bf16* p) {
    uint4 u = __ldg((const uint4*)p);
    f8 r;
    float2 a = __bfloat1622float2(*(__nv_bfloat162*)&u.x);
    float2 b = __bfloat1622float2(*(__nv_bfloat162*)&u.y);
    float2 c = __bfloat1622float2(*(__nv_bfloat162*)&u.z);
    float2 d = __bfloat1622float2(*(__nv_bfloat162*)&u.w);
    r.v[0] = a.x; r.v[1] = a.y; r.v[2] = b.x; r.v[3] = b.y;
    r.v[4] = c.x; r.v[5] = c.y; r.v[6] = d.x; r.v[7] = d.y;
    return r;
}
// gelu via HW tanh
__device__ __forceinline__ float gelu_t(float x) {
    float u = 0.7978845608f * x * fmaf(0.044715f, x * x, 1.0f);
    float t;
    asm("tanh.approx.f32 %0, %1;" : "=f"(t) : "f"(u));
    return 0.5f * x * (1.0f + t);
}

// ---------------------------------------------------------------------------
// LN of ROWS rows -> plain bf16 SW128 A region at smem offset 0.
// ---------------------------------------------------------------------------
template <bool GATHER, int ROWS>
__device__ __forceinline__ void ln_to_smem(
    const float* __restrict__ in, const float* __restrict__ gamma,
    const float* __restrict__ beta, char* smem, int rowBase)
{
    const int tid = threadIdx.x, lane = tid & 31, wid = tid >> 5;
    const float4 g = *(const float4*)(gamma + lane * 4);
    const float4 b = *(const float4*)(beta  + lane * 4);
    const uint32_t colOff = (uint32_t)((lane & 15) * 8);
    char* dhi = smem + (lane >> 4) * (ROWS * 128);
#pragma unroll 4
    for (int r = wid; r < ROWS; r += 8) {
        int src = GATHER ? orig_of(rowBase + r) : (rowBase + r);
        float4 v = __ldg((const float4*)(in + (size_t)src * 128 + lane * 4));
        float s = v.x + v.y + v.z + v.w;
        float q = v.x * v.x + v.y * v.y + v.z * v.z + v.w * v.w;
#pragma unroll
        for (int o = 16; o; o >>= 1) {
            s += __shfl_xor_sync(0xffffffffu, s, o);
            q += __shfl_xor_sync(0xffffffffu, q, o);
        }
        float mean = s * (1.0f / 128.0f);
        float rstd = rsqrtf(q * (1.0f / 128.0f) - mean * mean + 1e-5f);
        float o0 = (v.x - mean) * rstd * g.x + b.x;
        float o1 = (v.y - mean) * rstd * g.y + b.y;
        float o2 = (v.z - mean) * rstd * g.z + b.z;
        float o3 = (v.w - mean) * rstd * g.w + b.w;
        uint32_t o16 = SWZ128((uint32_t)(r * 128) + colOff);
        *(uint2*)(dhi + o16) = make_uint2(pk2(o0, o1), pk2(o2, o3));
    }
}

// ---------------------------------------------------------------------------
// cp.async one 128(N) x 64(k) bf16 weight chunk -> 16KB SW128 region.
// ---------------------------------------------------------------------------
__device__ __forceinline__ void load_wk64(
    uint32_t dst, const bf16* __restrict__ w,
    int rowOff, int kOff, int kStride)
{
    const int tid = threadIdx.x, c16 = tid & 7;
#pragma unroll
    for (int it = 0; it < 4; it++) {
        int row = (tid >> 3) + it * 32;
        uint32_t d = dst + SWZ128((uint32_t)(row * 128 + c16 * 16));
        CP_ASYNC16(d, w + (size_t)(rowOff + row) * kStride + kOff + c16 * 8);
    }
    CP_COMMIT();
}

// ---------------------------------------------------------------------------
// k64 chunk warp MMA, 1-pass.
// ---------------------------------------------------------------------------
template <int MT>
__device__ __forceinline__ void mma_k64(
    float4 (&acc)[MT][4], uint32_t aBase, uint32_t bBase)
{
    const int lane = threadIdx.x & 31, wid = threadIdx.x >> 5;
    const int warp_m = wid >> 2, warp_n = wid & 3;
    const int arow = warp_m * (MT * 16) + (lane & 15);
    const int akb  = (lane >> 4) * 8;
    const int brow = warp_n * 32 + ((lane >> 4) & 1) * 8 + (lane & 7);
    const int bkb  = ((lane >> 3) & 1) * 8;
#pragma unroll
    for (int ks = 0; ks < 4; ks++) {
        const int kA = (ks * 16 + akb) * 2;
        const int kB = (ks * 16 + bkb) * 2;
        uint32_t bh[2][4];
#pragma unroll
        for (int i = 0; i < 2; i++) {
            uint32_t boff = SWZ128((uint32_t)((brow + i * 16) * 128 + kB));
            ldsm4(bh[i], bBase + boff);
        }
#pragma unroll
        for (int mt = 0; mt < MT; mt++) {
            uint32_t aoff = SWZ128((uint32_t)((arow + mt * 16) * 128 + kA));
            uint32_t ah[4];
            ldsm4(ah, aBase + aoff);
#pragma unroll
            for (int nt = 0; nt < 4; nt++)
                mma_bf16(acc[mt][nt], ah, &bh[nt >> 1][(nt & 1) * 2]);
        }
    }
}

// ---------------------------------------------------------------------------
// Weight transpose: w[K,N] fp32 -> [N,K] bf16 (all 4 weights, one launch)
// ---------------------------------------------------------------------------
__global__ void wconv_all(
    const float* __restrict__ qkv_w, const float* __restrict__ proj_w,
    const float* __restrict__ w1, const float* __restrict__ w2,
    bf16* wq, bf16* wp, bf16* w1b, bf16* w2b)
{
    int idx = blockIdx.x * 256 + threadIdx.x;   // 131072 total
    const float* w; bf16* o; int K, N;
    if (idx < 49152)       { w = qkv_w;  o = wq;  K = 128; N = 384; }
    else if (idx < 65536)  { idx -= 49152; w = proj_w; o = wp;  K = 128; N = 128; }
    else if (idx < 98304)  { idx -= 65536; w = w1; o = w1b; K = 128; N = 256; }
    else                   { idx -= 98304; w = w2; o = w2b; K = 256; N = 128; }
    int n = idx / K, k = idx - n * K;
    o[idx] = __float2bfloat16(w[(size_t)k * N + n]);
}

// ---------------------------------------------------------------------------
// Kernel 1: LN1(+gather) + qkv GEMM -> bf16 qkv.
// A 32KB @0 | W 5x16KB @32768 -> 112KB.  6 k64 chunks, 3 rounds (one barrier
// each); chunk 5 reuses buffer 0, issued after round-1 barrier (race-free).
// ---------------------------------------------------------------------------
__global__ __launch_bounds__(256, 2) void qkv_kernel(
    const float* __restrict__ x, const float* __restrict__ g1,
    const float* __restrict__ b1, const bf16* __restrict__ wq,
    const float* __restrict__ qkv_b, bf16* __restrict__ qkv)
{
    extern __shared__ char smem[];
    const uint32_t sb = smem_u32(smem);
    const int tid = threadIdx.x, lane = tid & 31, wid = tid >> 5;
    const int warp_m = wid >> 2, warp_n = wid & 3;
    const int rowBase = blockIdx.x << 7;
    const int r4 = lane >> 2, c2 = (lane & 3) * 2;

    auto issueW = [&](int c) {
        load_wk64(sb + 32768 + (c % 5) * 16384, wq,
                  (c >> 1) * 128, (c & 1) * 64, 128);
    };

    issueW(0);
    ln_to_smem<true, 128>(x, g1, b1, smem, rowBase);
    issueW(1); issueW(2); issueW(3); issueW(4);

#pragma unroll
    for (int p = 0; p < 3; p++) {
        float4 acc[4][4];
#pragma unroll
        for (int i = 0; i < 4; i++)
#pragma unroll
            for (int j = 0; j < 4; j++) acc[i][j] = make_float4(0, 0, 0, 0);

        if (p == 0)      CP_WAIT(3);   // chunks 0,1 done
        else if (p == 1) CP_WAIT(1);   // chunks 2,3 done
        else             CP_WAIT(0);   // chunks 4,5 done
        __syncthreads();
        if (p == 1) issueW(5);         // buffer 0 reuse; all warps past round 0
        mma_k64<4>(acc, sb,         sb + 32768 + ((2 * p)     % 5) * 16384);
        mma_k64<4>(acc, sb + 16384, sb + 32768 + ((2 * p + 1) % 5) * 16384);

        const float scale = (p == 0) ? 0.25f : 1.0f;
#pragma unroll
        for (int mt = 0; mt < 4; mt++)
#pragma unroll
            for (int half = 0; half < 2; half++) {
                const int gr = rowBase + warp_m * 64 + mt * 16 + r4 + half * 8;
#pragma unroll
                for (int nt = 0; nt < 4; nt++) {
                    const int col = p * 128 + warp_n * 32 + nt * 8 + c2;
                    float v0 = half ? acc[mt][nt].z : acc[mt][nt].x;
                    float v1 = half ? acc[mt][nt].w : acc[mt][nt].y;
                    v0 = (v0 + __ldg(qkv_b + col)) * scale;
                    v1 = (v1 + __ldg(qkv_b + col + 1)) * scale;
                    *(uint32_t*)(qkv + (size_t)gr * 384 + col) = pk2(v0, v1);
                }
            }
    }
}

// ---------------------------------------------------------------------------
// Kernel 2: window attention (bf16 qkv, 16B loads) + proj GEMM + residual.
// O 32KB @0 | W 2x16KB static @32768 -> 64KB.  1 wait + 1 barrier.
// ---------------------------------------------------------------------------
__global__ __launch_bounds__(256, 2) void attnproj_kernel(
    const bf16* __restrict__ qkv, const float* __restrict__ rpb,
    const bf16* __restrict__ wp, const float* __restrict__ proj_b,
    const float* __restrict__ x, float* __restrict__ h2)
{
    extern __shared__ char smem[];
    const uint32_t sb = smem_u32(smem);
    const int tid = threadIdx.x, lane = tid & 31, wid = tid >> 5;
    const int warp_m = wid >> 2, warp_n = wid & 3;
    const int rowBase = blockIdx.x << 7;
    const int win0    = blockIdx.x << 5;
    const int h = lane >> 2, i = lane & 3;
    const int dy1 = i >> 1, dx1 = i & 1;

    load_wk64(sb + 32768, wp, 0, 0,  128);   // both W chunks up front
    load_wk64(sb + 49152, wp, 0, 64, 128);

    // ---- attention: each warp handles 4 windows ----------------------------
#pragma unroll
    for (int t = 0; t < 4; t++) {
        const int wl  = wid * 4 + t;
        const int win = win0 + wl;
        const int w   = win & 4095;
        const bool mr = ((w >> 6) == 63);
        const bool mc = ((w & 63) == 63);
        const bf16* base = qkv + (size_t)win * (4 * 384);

        float q[16];
        {
            f8 a = ld8bf(base + i * 384 + h * 16);
            f8 b = ld8bf(base + i * 384 + h * 16 + 8);
#pragma unroll
            for (int d = 0; d < 8; d++) { q[d] = a.v[d]; q[8 + d] = b.v[d]; }
        }
        float s[4];
#pragma unroll
        for (int j = 0; j < 4; j++) {
            f8 ka = ld8bf(base + j * 384 + 128 + h * 16);
            f8 kb = ld8bf(base + j * 384 + 128 + h * 16 + 8);
            float a = 0.0f;
#pragma unroll
            for (int d = 0; d < 8; d++)
                a += q[d] * ka.v[d] + q[8 + d] * kb.v[d];
            int dy2 = j >> 1, dx2 = j & 1;
            bool ok = (!mr || dy1 == dy2) && (!mc || dx1 == dx2);
            s[j] = a + __ldg(rpb + ((dy1 - dy2 + 1) * 3 + (dx1 - dx2 + 1)) * 8 + h)
                 + (ok ? 0.0f : -100.0f);
        }
        float mx = fmaxf(fmaxf(s[0], s[1]), fmaxf(s[2], s[3]));
        float p[4], sum = 0.0f;
#pragma unroll
        for (int j = 0; j < 4; j++) { p[j] = expf(s[j] - mx); sum += p[j]; }
        float inv = 1.0f / sum;

        float ov[16];
#pragma unroll
        for (int d = 0; d < 16; d++) ov[d] = 0.0f;
#pragma unroll
        for (int j = 0; j < 4; j++) {
            f8 va = ld8bf(base + j * 384 + 256 + h * 16);
            f8 vb = ld8bf(base + j * 384 + 256 + h * 16 + 8);
            float pj = p[j] * inv;
#pragma unroll
            for (int d = 0; d < 8; d++) {
                ov[d]     += pj * va.v[d];
                ov[8 + d] += pj * vb.v[d];
            }
        }
        const int row = wl * 4 + i;
#pragma unroll
        for (int d4 = 0; d4 < 4; d4++) {
            const int ch = h * 16 + d4 * 4;
            char* dst = smem + (ch >> 6) * 16384;
            uint32_t o16 = SWZ128((uint32_t)(row * 128 + (ch & 63) * 2));
            *(uint2*)(dst + o16) = make_uint2(pk2(ov[d4 * 4], ov[d4 * 4 + 1]),
                                              pk2(ov[d4 * 4 + 2], ov[d4 * 4 + 3]));
        }
    }

    // ---- proj GEMM: single wait + barrier, then both chunks -----------------
    float4 acc[4][4];
#pragma unroll
    for (int a = 0; a < 4; a++)
#pragma unroll
        for (int j = 0; j < 4; j++) acc[a][j] = make_float4(0, 0, 0, 0);

    CP_WAIT(0);
    __syncthreads();
    mma_k64<4>(acc, sb,         sb + 32768);
    mma_k64<4>(acc, sb + 16384, sb + 49152);

    const int r4 = lane >> 2, c2 = (lane & 3) * 2;
#pragma unroll
    for (int mt = 0; mt < 4; mt++)
#pragma unroll
        for (int half = 0; half < 2; half++) {
            const int gr = rowBase + warp_m * 64 + mt * 16 + r4 + half * 8;
            const size_t outRow = (size_t)orig_of(gr);
#pragma unroll
            for (int nt = 0; nt < 4; nt++) {
                const int col = warp_n * 32 + nt * 8 + c2;
                float v0 = half ? acc[mt][nt].z : acc[mt][nt].x;
                float v1 = half ? acc[mt][nt].w : acc[mt][nt].y;
                const float2 sk = *(const float2*)(x + outRow * 128 + col);
                v0 += __ldg(proj_b + col) + sk.x;
                v1 += __ldg(proj_b + col + 1) + sk.y;
                *(float2*)(h2 + outRow * 128 + col) = make_float2(v0, v1);
            }
        }
}

// ---------------------------------------------------------------------------
// Kernel 3: LN2 + MLP1(GELU) + MLP2 + residual, M=128 tiles (MT=4).
// smem: L2A 2x16KB @0 (M1 k-chunks 2,3 overwrite it) | M1 k-chunks 0,1
//       @32768,49152 | W 3x16KB @65536  -> 114688.  8 k64 chunks. (R12)
// ---------------------------------------------------------------------------
__global__ __launch_bounds__(256, 2) void mlp_kernel(
    const float* __restrict__ h2, const float* __restrict__ g2,
    const float* __restrict__ b2,
    const bf16* __restrict__ w1, const float* __restrict__ bb1,
    const bf16* __restrict__ w2, const float* __restrict__ bb2,
    float* __restrict__ out)
{
    extern __shared__ char smem[];
    const uint32_t sb = smem_u32(smem);
    const int tid = threadIdx.x, lane = tid & 31, wid = tid >> 5;
    const int warp_m = wid >> 2, warp_n = wid & 3;
    const int rowBase = blockIdx.x << 7;
    const int r4 = lane >> 2, c2 = (lane & 3) * 2;

    auto issueW = [&](int c) {
        const uint32_t dst = sb + 65536 + (c % 3) * 16384;
        if (c < 2)      load_wk64(dst, w1, 0,   (c & 1) * 64, 128);
        else if (c < 4) load_wk64(dst, w1, 128, (c & 1) * 64, 128);
        else            load_wk64(dst, w2, 0,   (c - 4) * 64, 256);
    };

    issueW(0);
    ln_to_smem<false, 128>(h2, g2, b2, smem, rowBase);
    issueW(1);

    // ---- mlp1: 2 N-passes (acc1 reused), gelu -> M1 chunks ------------------
#pragma unroll
    for (int pass = 0; pass < 2; pass++) {
        float4 acc1[4][4];
#pragma unroll
        for (int a = 0; a < 4; a++)
#pragma unroll
            for (int j = 0; j < 4; j++) acc1[a][j] = make_float4(0, 0, 0, 0);
#pragma unroll
        for (int h = 0; h < 2; h++) {
            const int c = pass * 2 + h;
            CP_WAIT(1);
            __syncthreads();
            mma_k64<4>(acc1, sb + h * 16384, sb + 65536 + (c % 3) * 16384);
            issueW(c + 2);
        }
        if (pass == 1) __syncthreads();   // all warps done reading L2A
        const uint32_t m1base = (pass == 0) ? 32768u : 0u;
#pragma unroll
        for (int mt = 0; mt < 4; mt++)
#pragma unroll
            for (int half = 0; half < 2; half++) {
                const int row = warp_m * 64 + mt * 16 + r4 + half * 8;
#pragma unroll
                for (int nt = 0; nt < 4; nt++) {
                    const int ch = warp_n * 32 + nt * 8 + c2;
                    float v0 = half ? acc1[mt][nt].z : acc1[mt][nt].x;
                    float v1 = half ? acc1[mt][nt].w : acc1[mt][nt].y;
                    v0 = gelu_t(v0 + __ldg(bb1 + pass * 128 + ch));
                    v1 = gelu_t(v1 + __ldg(bb1 + pass * 128 + ch + 1));
                    char* dst = smem + m1base + (ch >> 6) * 16384;
                    uint32_t o16 = SWZ128((uint32_t)(row * 128 + (ch & 63) * 2));
                    *(uint32_t*)(dst + o16) = pk2(v0, v1);
                }
            }
    }

    // ---- mlp2: K=256 over M1 chunks {32768,49152,0,16384} --------------------
    float4 acc2[4][4];
#pragma unroll
    for (int a = 0; a < 4; a++)
#pragma unroll
        for (int j = 0; j < 4; j++) acc2[a][j] = make_float4(0, 0, 0, 0);

    const uint32_t m1chunk[4] = { 32768u, 49152u, 0u, 16384u };
#pragma unroll
    for (int j = 0; j < 4; j++) {
        const int c = 4 + j;
        if (c == 7) CP_WAIT(0); else CP_WAIT(1);
        __syncthreads();
        mma_k64<4>(acc2, sb + m1chunk[j], sb + 65536 + (c % 3) * 16384);
        if (c + 2 <= 7) issueW(c + 2);
    }

    // ---- epilogue: out = acc2 + b2 + h2 -------------------------------------
#pragma unroll
    for (int mt = 0; mt < 4; mt++)
#pragma unroll
        for (int half = 0; half < 2; half++) {
            const int gr = rowBase + warp_m * 64 + mt * 16 + r4 + half * 8;
#pragma unroll
            for (int nt = 0; nt < 4; nt++) {
                const int col = warp_n * 32 + nt * 8 + c2;
                float v0 = half ? acc2[mt][nt].z : acc2[mt][nt].x;
                float v1 = half ? acc2[mt][nt].w : acc2[mt][nt].y;
                const float2 sk = *(const float2*)(h2 + (size_t)gr * 128 + col);
                v0 += __ldg(bb2 + col) + sk.x;
                v1 += __ldg(bb2 + col + 1) + sk.y;
                *(float2*)(out + (size_t)gr * 128 + col) = make_float2(v0, v1);
            }
        }
}

// ---------------------------------------------------------------------------
extern "C" void kernel_launch(void* const* d_in, const int* in_sizes, int n_in,
                              void* d_out, int out_size)
{
    const float* x      = (const float*)d_in[0];
    const float* qkv_w  = (const float*)d_in[1];
    const float* qkv_b  = (const float*)d_in[2];
    const float* proj_w = (const float*)d_in[3];
    const float* proj_b = (const float*)d_in[4];
    const float* rpb    = (const float*)d_in[5];
    const float* g1     = (const float*)d_in[6];
    const float* b1     = (const float*)d_in[7];
    const float* g2     = (const float*)d_in[8];
    const float* b2     = (const float*)d_in[9];
    const float* w1     = (const float*)d_in[10];
    const float* bb1    = (const float*)d_in[11];
    const float* w2     = (const float*)d_in[12];
    const float* bb2    = (const float*)d_in[13];
    float* out = (float*)d_out;

    float *h2;
    bf16 *qkv, *wq, *wp, *w1b, *w2b;
    cudaGetSymbolAddress((void**)&qkv, g_qkv);
    cudaGetSymbolAddress((void**)&h2,  g_h2);
    cudaGetSymbolAddress((void**)&wq,  g_wq);
    cudaGetSymbolAddress((void**)&wp,  g_wp);
    cudaGetSymbolAddress((void**)&w1b, g_w1);
    cudaGetSymbolAddress((void**)&w2b, g_w2);

    cudaFuncSetAttribute(qkv_kernel,      cudaFuncAttributeMaxDynamicSharedMemorySize, 114688);
    cudaFuncSetAttribute(attnproj_kernel, cudaFuncAttributeMaxDynamicSharedMemorySize, 65536);
    cudaFuncSetAttribute(mlp_kernel,      cudaFuncAttributeMaxDynamicSharedMemorySize, 114688);

    wconv_all<<<512, 256>>>(qkv_w, proj_w, w1, w2, wq, wp, w1b, w2b);

    qkv_kernel<<<TOK / 128, 256, 114688>>>(x, g1, b1, wq, qkv_b, qkv);
    attnproj_kernel<<<TOK / 128, 256, 65536>>>(qkv, rpb, wp, proj_b, x, h2);
    mlp_kernel<<<TOK / 128, 256, 114688>>>(h2, g2, b2, w1b, bb1, w2b, bb2, out);
}

// round 14
// speedup vs baseline: 1.0631x; 1.0631x over previous
#include <cuda_runtime.h>
#include <cuda_bf16.h>
#include <math.h>
#include <stdint.h>

// ---------------------------------------------------------------------------
// Swin block: B=32, H=W=128, C=128, WS=2, SS=1, NH=8, HD=16
// K1 (qkv) / K2 (attnproj): R10 best-known config, 2 CTA/SM.
// K3 (mlp): R14 occupancy experiment — M=64, MT=2, 72KB smem, 3 CTA/SM.
// GEMMs: mma.sync plain bf16 1-pass.
// ---------------------------------------------------------------------------

#define TOK   524288

typedef __nv_bfloat16 bf16;

__device__ bf16  g_qkv[(size_t)TOK * 384];   // bf16 qkv (q pre-scaled)
__device__ float g_h2 [(size_t)TOK * 128];
// weights transposed to [N,K] bf16
__device__ bf16  g_wq[384 * 128];
__device__ bf16  g_wp[128 * 128];
__device__ bf16  g_w1[256 * 128];
__device__ bf16  g_w2[128 * 256];

// ---------------------------------------------------------------------------
__device__ __forceinline__ uint32_t smem_u32(const void* p) {
    uint32_t a;
    asm("{ .reg .u64 t; cvta.to.shared.u64 t, %1; cvt.u32.u64 %0, t; }"
        : "=r"(a) : "l"(p));
    return a;
}

#define SWZ128(o) ((o) ^ (((o) >> 3) & 0x70))
#define SWZ64(o)  ((o) ^ (((o) >> 3) & 0x30))

#define CP_ASYNC16(dst, src) \
    asm volatile("cp.async.cg.shared.global [%0], [%1], 16;" \
                 :: "r"(dst), "l"(src) : "memory")
#define CP_COMMIT()  asm volatile("cp.async.commit_group;" ::: "memory")
#define CP_WAIT0()   asm volatile("cp.async.wait_group 0;" ::: "memory")
#define CP_WAIT1()   asm volatile("cp.async.wait_group 1;" ::: "memory")

__device__ __forceinline__ void ldsm4(uint32_t r[4], uint32_t addr) {
    asm volatile("ldmatrix.sync.aligned.m8n8.x4.shared.b16 {%0,%1,%2,%3}, [%4];"
                 : "=r"(r[0]), "=r"(r[1]), "=r"(r[2]), "=r"(r[3]) : "r"(addr));
}

__device__ __forceinline__ void mma_bf16(float4& d, const uint32_t a[4],
                                         const uint32_t b[2]) {
    asm volatile(
        "mma.sync.aligned.m16n8k16.row.col.f32.bf16.bf16.f32 "
        "{%0,%1,%2,%3}, {%4,%5,%6,%7}, {%8,%9}, {%0,%1,%2,%3};"
        : "+f"(d.x), "+f"(d.y), "+f"(d.z), "+f"(d.w)
        : "r"(a[0]), "r"(a[1]), "r"(a[2]), "r"(a[3]), "r"(b[0]), "r"(b[1]));
}

__device__ __forceinline__ int orig_of(int r) {
    int win = r >> 2, s = r & 3;
    int b  = win >> 12;
    int w  = win & 4095;
    int wh = w >> 6, ww = w & 63;
    int ii = ((wh << 1) + (s >> 1) + 1) & 127;
    int jj = ((ww << 1) + (s & 1) + 1) & 127;
    return (b << 14) + (ii << 7) + jj;
}

__device__ __forceinline__ uint32_t pk2(float a, float b) {
    __nv_bfloat162 t = __floats2bfloat162_rn(a, b);
    return *(uint32_t*)&t;
}
__device__ __forceinline__ float4 ld4bf(const bf16* p) {
    uint2 u = __ldg((const uint2*)p);
    float2 fa = __bfloat1622float2(*(__nv_bfloat162*)&u.x);
    float2 fb = __bfloat1622float2(*(__nv_bfloat162*)&u.y);
    return make_float4(fa.x, fa.y, fb.x, fb.y);
}
// gelu via HW tanh
__device__ __forceinline__ float gelu_t(float x) {
    float u = 0.7978845608f * x * fmaf(0.044715f, x * x, 1.0f);
    float t;
    asm("tanh.approx.f32 %0, %1;" : "=f"(t) : "f"(u));
    return 0.5f * x * (1.0f + t);
}

// ---------------------------------------------------------------------------
// LN of ROWS rows -> plain bf16 SW128 A region at smem offset 0.
// Layout: 2 k64-chunks of ROWS*128 bytes each.
// ---------------------------------------------------------------------------
template <bool GATHER, int ROWS>
__device__ __forceinline__ void ln_to_smem(
    const float* __restrict__ in, const float* __restrict__ gamma,
    const float* __restrict__ beta, char* smem, int rowBase)
{
    const int tid = threadIdx.x, lane = tid & 31, wid = tid >> 5;
    const float4 g = *(const float4*)(gamma + lane * 4);
    const float4 b = *(const float4*)(beta  + lane * 4);
    const uint32_t colOff = (uint32_t)((lane & 15) * 8);
    char* dhi = smem + (lane >> 4) * (ROWS * 128);
#pragma unroll 4
    for (int r = wid; r < ROWS; r += 8) {
        int src = GATHER ? orig_of(rowBase + r) : (rowBase + r);
        float4 v = __ldg((const float4*)(in + (size_t)src * 128 + lane * 4));
        float s = v.x + v.y + v.z + v.w;
        float q = v.x * v.x + v.y * v.y + v.z * v.z + v.w * v.w;
#pragma unroll
        for (int o = 16; o; o >>= 1) {
            s += __shfl_xor_sync(0xffffffffu, s, o);
            q += __shfl_xor_sync(0xffffffffu, q, o);
        }
        float mean = s * (1.0f / 128.0f);
        float rstd = rsqrtf(q * (1.0f / 128.0f) - mean * mean + 1e-5f);
        float o0 = (v.x - mean) * rstd * g.x + b.x;
        float o1 = (v.y - mean) * rstd * g.y + b.y;
        float o2 = (v.z - mean) * rstd * g.z + b.z;
        float o3 = (v.w - mean) * rstd * g.w + b.w;
        uint32_t o16 = SWZ128((uint32_t)(r * 128) + colOff);
        *(uint2*)(dhi + o16) = make_uint2(pk2(o0, o1), pk2(o2, o3));
    }
}

// ---------------------------------------------------------------------------
// cp.async one 128(N) x 64(k) bf16 weight chunk -> 16KB SW128 region.
// ---------------------------------------------------------------------------
__device__ __forceinline__ void load_wk64(
    uint32_t dst, const bf16* __restrict__ w,
    int rowOff, int kOff, int kStride)
{
    const int tid = threadIdx.x, c16 = tid & 7;
#pragma unroll
    for (int it = 0; it < 4; it++) {
        int row = (tid >> 3) + it * 32;
        uint32_t d = dst + SWZ128((uint32_t)(row * 128 + c16 * 16));
        CP_ASYNC16(d, w + (size_t)(rowOff + row) * kStride + kOff + c16 * 8);
    }
    CP_COMMIT();
}

// cp.async one 128(N) x 32(k) bf16 weight chunk -> 8KB SW64 region.
__device__ __forceinline__ void load_wk32(
    uint32_t dst, const bf16* __restrict__ w,
    int rowOff, int kOff, int kStride)
{
    const int tid = threadIdx.x, c16 = tid & 3;
#pragma unroll
    for (int it = 0; it < 2; it++) {
        int row = (tid >> 2) + it * 64;
        uint32_t d = dst + SWZ64((uint32_t)(row * 64 + c16 * 16));
        CP_ASYNC16(d, w + (size_t)(rowOff + row) * kStride + kOff + c16 * 8);
    }
    CP_COMMIT();
}

// ---------------------------------------------------------------------------
// k64 chunk warp MMA (A SW128 k64 region; B 16KB SW128 chunk).
// ---------------------------------------------------------------------------
template <int MT>
__device__ __forceinline__ void mma_k64(
    float4 (&acc)[MT][4], uint32_t aBase, uint32_t bBase)
{
    const int lane = threadIdx.x & 31, wid = threadIdx.x >> 5;
    const int warp_m = wid >> 2, warp_n = wid & 3;
    const int arow = warp_m * (MT * 16) + (lane & 15);
    const int akb  = (lane >> 4) * 8;
    const int brow = warp_n * 32 + ((lane >> 4) & 1) * 8 + (lane & 7);
    const int bkb  = ((lane >> 3) & 1) * 8;
#pragma unroll
    for (int ks = 0; ks < 4; ks++) {
        const int kA = (ks * 16 + akb) * 2;
        const int kB = (ks * 16 + bkb) * 2;
        uint32_t bh[2][4];
#pragma unroll
        for (int i = 0; i < 2; i++) {
            uint32_t boff = SWZ128((uint32_t)((brow + i * 16) * 128 + kB));
            ldsm4(bh[i], bBase + boff);
        }
#pragma unroll
        for (int mt = 0; mt < MT; mt++) {
            uint32_t aoff = SWZ128((uint32_t)((arow + mt * 16) * 128 + kA));
            uint32_t ah[4];
            ldsm4(ah, aBase + aoff);
#pragma unroll
            for (int nt = 0; nt < 4; nt++)
                mma_bf16(acc[mt][nt], ah, &bh[nt >> 1][(nt & 1) * 2]);
        }
    }
}

// k32 half-chunk warp MMA (A SW128 k64 region, khalf picks k-half;
// B 8KB SW64 k32 chunk).
template <int MT>
__device__ __forceinline__ void mma_k32(
    float4 (&acc)[MT][4], uint32_t aBase, int khalf, uint32_t bBase)
{
    const int lane = threadIdx.x & 31, wid = threadIdx.x >> 5;
    const int warp_m = wid >> 2, warp_n = wid & 3;
    const int arow = warp_m * (MT * 16) + (lane & 15);
    const int akb  = (lane >> 4) * 8;
    const int brow = warp_n * 32 + ((lane >> 4) & 1) * 8 + (lane & 7);
    const int bkb  = ((lane >> 3) & 1) * 8;
#pragma unroll
    for (int ks = 0; ks < 2; ks++) {
        const int kA = (khalf * 32 + ks * 16 + akb) * 2;
        const int kB = (ks * 16 + bkb) * 2;
        uint32_t bh[2][4];
#pragma unroll
        for (int i = 0; i < 2; i++) {
            uint32_t boff = SWZ64((uint32_t)((brow + i * 16) * 64 + kB));
            ldsm4(bh[i], bBase + boff);
        }
#pragma unroll
        for (int mt = 0; mt < MT; mt++) {
            uint32_t aoff = SWZ128((uint32_t)((arow + mt * 16) * 128 + kA));
            uint32_t ah[4];
            ldsm4(ah, aBase + aoff);
#pragma unroll
            for (int nt = 0; nt < 4; nt++)
                mma_bf16(acc[mt][nt], ah, &bh[nt >> 1][(nt & 1) * 2]);
        }
    }
}

// ---------------------------------------------------------------------------
// Weight transpose: w[K,N] fp32 -> [N,K] bf16 (all 4 weights, one launch)
// ---------------------------------------------------------------------------
__global__ void wconv_all(
    const float* __restrict__ qkv_w, const float* __restrict__ proj_w,
    const float* __restrict__ w1, const float* __restrict__ w2,
    bf16* wq, bf16* wp, bf16* w1b, bf16* w2b)
{
    int idx = blockIdx.x * 256 + threadIdx.x;   // 131072 total
    const float* w; bf16* o; int K, N;
    if (idx < 49152)       { w = qkv_w;  o = wq;  K = 128; N = 384; }
    else if (idx < 65536)  { idx -= 49152; w = proj_w; o = wp;  K = 128; N = 128; }
    else if (idx < 98304)  { idx -= 65536; w = w1; o = w1b; K = 128; N = 256; }
    else                   { idx -= 98304; w = w2; o = w2b; K = 256; N = 128; }
    int n = idx / K, k = idx - n * K;
    o[idx] = __float2bfloat16(w[(size_t)k * N + n]);
}

// ---------------------------------------------------------------------------
// Kernel 1: LN1(+gather) + qkv GEMM -> bf16 qkv.  (R10 verbatim)
// A 32KB @0 | W 3x16KB @32768 -> 80KB.  6 k64 chunks, 3-stage.
// ---------------------------------------------------------------------------
__global__ __launch_bounds__(256, 2) void qkv_kernel(
    const float* __restrict__ x, const float* __restrict__ g1,
    const float* __restrict__ b1, const bf16* __restrict__ wq,
    const float* __restrict__ qkv_b, bf16* __restrict__ qkv)
{
    extern __shared__ char smem[];
    const uint32_t sb = smem_u32(smem);
    const int tid = threadIdx.x, lane = tid & 31, wid = tid >> 5;
    const int warp_m = wid >> 2, warp_n = wid & 3;
    const int rowBase = blockIdx.x << 7;
    const int r4 = lane >> 2, c2 = (lane & 3) * 2;

    auto issueW = [&](int c) {
        load_wk64(sb + 32768 + (c % 3) * 16384, wq,
                  (c >> 1) * 128, (c & 1) * 64, 128);
    };

    issueW(0);
    ln_to_smem<true, 128>(x, g1, b1, smem, rowBase);
    issueW(1);

#pragma unroll
    for (int p = 0; p < 3; p++) {
        float4 acc[4][4];
#pragma unroll
        for (int i = 0; i < 4; i++)
#pragma unroll
            for (int j = 0; j < 4; j++) acc[i][j] = make_float4(0, 0, 0, 0);
#pragma unroll
        for (int h = 0; h < 2; h++) {
            const int c = p * 2 + h;
            if (c == 5) CP_WAIT0(); else CP_WAIT1();
            __syncthreads();
            mma_k64<4>(acc, sb + h * 16384, sb + 32768 + (c % 3) * 16384);
            if (c + 2 <= 5) issueW(c + 2);
        }
        const float scale = (p == 0) ? 0.25f : 1.0f;
#pragma unroll
        for (int mt = 0; mt < 4; mt++)
#pragma unroll
            for (int half = 0; half < 2; half++) {
                const int gr = rowBase + warp_m * 64 + mt * 16 + r4 + half * 8;
#pragma unroll
                for (int nt = 0; nt < 4; nt++) {
                    const int col = p * 128 + warp_n * 32 + nt * 8 + c2;
                    float v0 = half ? acc[mt][nt].z : acc[mt][nt].x;
                    float v1 = half ? acc[mt][nt].w : acc[mt][nt].y;
                    v0 = (v0 + __ldg(qkv_b + col)) * scale;
                    v1 = (v1 + __ldg(qkv_b + col + 1)) * scale;
                    *(uint32_t*)(qkv + (size_t)gr * 384 + col) = pk2(v0, v1);
                }
            }
    }
}

// ---------------------------------------------------------------------------
// Kernel 2: window attention + proj GEMM + residual scatter.  (R10 verbatim)
// O 32KB @0 | W 2x16KB static @32768 -> 64KB.
// ---------------------------------------------------------------------------
__global__ __launch_bounds__(256, 2) void attnproj_kernel(
    const bf16* __restrict__ qkv, const float* __restrict__ rpb,
    const bf16* __restrict__ wp, const float* __restrict__ proj_b,
    const float* __restrict__ x, float* __restrict__ h2)
{
    extern __shared__ char smem[];
    const uint32_t sb = smem_u32(smem);
    const int tid = threadIdx.x, lane = tid & 31, wid = tid >> 5;
    const int warp_m = wid >> 2, warp_n = wid & 3;
    const int rowBase = blockIdx.x << 7;
    const int win0    = blockIdx.x << 5;
    const int h = lane >> 2, i = lane & 3;
    const int dy1 = i >> 1, dx1 = i & 1;

    load_wk64(sb + 32768, wp, 0, 0, 128);    // W chunk 0 (k 0-63)

    // ---- attention: each warp handles 4 windows ----------------------------
#pragma unroll
    for (int t = 0; t < 4; t++) {
        const int wl  = wid * 4 + t;
        const int win = win0 + wl;
        const int w   = win & 4095;
        const bool mr = ((w >> 6) == 63);
        const bool mc = ((w & 63) == 63);
        const bf16* base = qkv + (size_t)win * (4 * 384);

        float q[16];
        const bf16* qp = base + i * 384 + h * 16;
#pragma unroll
        for (int d4 = 0; d4 < 4; d4++) {
            float4 v = ld4bf(qp + d4 * 4);
            q[d4 * 4 + 0] = v.x; q[d4 * 4 + 1] = v.y;
            q[d4 * 4 + 2] = v.z; q[d4 * 4 + 3] = v.w;
        }
        float s[4];
#pragma unroll
        for (int j = 0; j < 4; j++) {
            const bf16* kp = base + j * 384 + 128 + h * 16;
            float a = 0.0f;
#pragma unroll
            for (int d4 = 0; d4 < 4; d4++) {
                float4 v = ld4bf(kp + d4 * 4);
                a += q[d4 * 4 + 0] * v.x + q[d4 * 4 + 1] * v.y
                   + q[d4 * 4 + 2] * v.z + q[d4 * 4 + 3] * v.w;
            }
            int dy2 = j >> 1, dx2 = j & 1;
            bool ok = (!mr || dy1 == dy2) && (!mc || dx1 == dx2);
            s[j] = a + __ldg(rpb + ((dy1 - dy2 + 1) * 3 + (dx1 - dx2 + 1)) * 8 + h)
                 + (ok ? 0.0f : -100.0f);
        }
        float mx = fmaxf(fmaxf(s[0], s[1]), fmaxf(s[2], s[3]));
        float p[4], sum = 0.0f;
#pragma unroll
        for (int j = 0; j < 4; j++) { p[j] = expf(s[j] - mx); sum += p[j]; }
        float inv = 1.0f / sum;

        float ov[16];
#pragma unroll
        for (int d = 0; d < 16; d++) ov[d] = 0.0f;
#pragma unroll
        for (int j = 0; j < 4; j++) {
            const bf16* vp = base + j * 384 + 256 + h * 16;
            float pj = p[j] * inv;
#pragma unroll
            for (int d4 = 0; d4 < 4; d4++) {
                float4 v = ld4bf(vp + d4 * 4);
                ov[d4 * 4 + 0] += pj * v.x; ov[d4 * 4 + 1] += pj * v.y;
                ov[d4 * 4 + 2] += pj * v.z; ov[d4 * 4 + 3] += pj * v.w;
            }
        }
        const int row = wl * 4 + i;
#pragma unroll
        for (int d4 = 0; d4 < 4; d4++) {
            const int ch = h * 16 + d4 * 4;
            char* dst = smem + (ch >> 6) * 16384;
            uint32_t o16 = SWZ128((uint32_t)(row * 128 + (ch & 63) * 2));
            *(uint2*)(dst + o16) = make_uint2(pk2(ov[d4 * 4], ov[d4 * 4 + 1]),
                                              pk2(ov[d4 * 4 + 2], ov[d4 * 4 + 3]));
        }
    }
    load_wk64(sb + 49152, wp, 0, 64, 128);   // W chunk 1 (k 64-127)

    // ---- proj GEMM (2 static chunks) ----------------------------------------
    float4 acc[4][4];
#pragma unroll
    for (int a = 0; a < 4; a++)
#pragma unroll
        for (int j = 0; j < 4; j++) acc[a][j] = make_float4(0, 0, 0, 0);

    CP_WAIT1();
    __syncthreads();
    mma_k64<4>(acc, sb, sb + 32768);
    CP_WAIT0();
    __syncthreads();
    mma_k64<4>(acc, sb + 16384, sb + 49152);

    const int r4 = lane >> 2, c2 = (lane & 3) * 2;
#pragma unroll
    for (int mt = 0; mt < 4; mt++)
#pragma unroll
        for (int half = 0; half < 2; half++) {
            const int gr = rowBase + warp_m * 64 + mt * 16 + r4 + half * 8;
            const size_t outRow = (size_t)orig_of(gr);
#pragma unroll
            for (int nt = 0; nt < 4; nt++) {
                const int col = warp_n * 32 + nt * 8 + c2;
                float v0 = half ? acc[mt][nt].z : acc[mt][nt].x;
                float v1 = half ? acc[mt][nt].w : acc[mt][nt].y;
                const float2 sk = *(const float2*)(x + outRow * 128 + col);
                v0 += __ldg(proj_b + col) + sk.x;
                v1 += __ldg(proj_b + col + 1) + sk.y;
                *(float2*)(h2 + outRow * 128 + col) = make_float2(v0, v1);
            }
        }
}

// ---------------------------------------------------------------------------
// Kernel 3: LN2 + MLP1(GELU) + MLP2 + residual.  R14: M=64, MT=2, 3 CTA/SM.
// smem: L2A 16KB @0 | M1 32KB @16384 (4 k64 chunks of 8KB) |
//       W 3x8KB @49152  -> 73728 total.  16 k32 chunks, 3-buffer rotation.
// ---------------------------------------------------------------------------
__global__ __launch_bounds__(256, 3) void mlp_kernel(
    const float* __restrict__ h2, const float* __restrict__ g2,
    const float* __restrict__ b2,
    const bf16* __restrict__ w1, const float* __restrict__ bb1,
    const bf16* __restrict__ w2, const float* __restrict__ bb2,
    float* __restrict__ out)
{
    extern __shared__ char smem[];
    const uint32_t sb = smem_u32(smem);
    const int tid = threadIdx.x, lane = tid & 31, wid = tid >> 5;
    const int warp_m = wid >> 2, warp_n = wid & 3;
    const int rowBase = blockIdx.x << 6;   // 64 rows per CTA
    const int r4 = lane >> 2, c2 = (lane & 3) * 2;

    auto issueW = [&](int c) {
        const uint32_t dst = sb + 49152 + (c % 3) * 8192;
        if (c < 8) load_wk32(dst, w1, (c >> 2) * 128, (c & 3) * 32, 128);
        else       load_wk32(dst, w2, 0, (c - 8) * 32, 256);
    };

    issueW(0);
    ln_to_smem<false, 64>(h2, g2, b2, smem, rowBase);
    issueW(1);

    // ---- mlp1: 2 N-passes x 4 k32 chunks; gelu -> M1 ------------------------
#pragma unroll
    for (int pass = 0; pass < 2; pass++) {
        float4 acc1[2][4];
#pragma unroll
        for (int a = 0; a < 2; a++)
#pragma unroll
            for (int j = 0; j < 4; j++) acc1[a][j] = make_float4(0, 0, 0, 0);
#pragma unroll
        for (int h = 0; h < 4; h++) {
            const int c = pass * 4 + h;
            CP_WAIT1();
            __syncthreads();
            mma_k32<2>(acc1, sb + (h >> 1) * 8192, h & 1,
                       sb + 49152 + (c % 3) * 8192);
            issueW(c + 2);     // c <= 7 -> c+2 <= 9 <= 15
        }
        // gelu epilogue -> M1 chunks (pass*2 + (ch>>6))
#pragma unroll
        for (int mt = 0; mt < 2; mt++)
#pragma unroll
            for (int half = 0; half < 2; half++) {
                const int row = warp_m * 32 + mt * 16 + r4 + half * 8;
#pragma unroll
                for (int nt = 0; nt < 4; nt++) {
                    const int ch = warp_n * 32 + nt * 8 + c2;   // 0..127 local
                    float v0 = half ? acc1[mt][nt].z : acc1[mt][nt].x;
                    float v1 = half ? acc1[mt][nt].w : acc1[mt][nt].y;
                    v0 = gelu_t(v0 + __ldg(bb1 + pass * 128 + ch));
                    v1 = gelu_t(v1 + __ldg(bb1 + pass * 128 + ch + 1));
                    char* dst = smem + 16384 + (pass * 2 + (ch >> 6)) * 8192;
                    uint32_t o16 = SWZ128((uint32_t)(row * 128 + (ch & 63) * 2));
                    *(uint32_t*)(dst + o16) = pk2(v0, v1);
                }
            }
    }

    // ---- mlp2: K=256 as 8 k32 chunks over M1 --------------------------------
    float4 acc2[2][4];
#pragma unroll
    for (int a = 0; a < 2; a++)
#pragma unroll
        for (int j = 0; j < 4; j++) acc2[a][j] = make_float4(0, 0, 0, 0);

#pragma unroll
    for (int j = 0; j < 4 * 2; j++) {
        const int c = 8 + j;
        if (c == 15) CP_WAIT0(); else CP_WAIT1();
        __syncthreads();   // also guards M1 gelu writes before first read
        mma_k32<2>(acc2, sb + 16384 + (j >> 1) * 8192, j & 1,
                   sb + 49152 + (c % 3) * 8192);
        if (c + 2 <= 15) issueW(c + 2);
    }

    // ---- epilogue: out = acc2 + b2 + h2 -------------------------------------
#pragma unroll
    for (int mt = 0; mt < 2; mt++)
#pragma unroll
        for (int half = 0; half < 2; half++) {
            const int gr = rowBase + warp_m * 32 + mt * 16 + r4 + half * 8;
#pragma unroll
            for (int nt = 0; nt < 4; nt++) {
                const int col = warp_n * 32 + nt * 8 + c2;
                float v0 = half ? acc2[mt][nt].z : acc2[mt][nt].x;
                float v1 = half ? acc2[mt][nt].w : acc2[mt][nt].y;
                const float2 sk = *(const float2*)(h2 + (size_t)gr * 128 + col);
                v0 += __ldg(bb2 + col) + sk.x;
                v1 += __ldg(bb2 + col + 1) + sk.y;
                *(float2*)(out + (size_t)gr * 128 + col) = make_float2(v0, v1);
            }
        }
}

// ---------------------------------------------------------------------------
extern "C" void kernel_launch(void* const* d_in, const int* in_sizes, int n_in,
                              void* d_out, int out_size)
{
    const float* x      = (const float*)d_in[0];
    const float* qkv_w  = (const float*)d_in[1];
    const float* qkv_b  = (const float*)d_in[2];
    const float* proj_w = (const float*)d_in[3];
    const float* proj_b = (const float*)d_in[4];
    const float* rpb    = (const float*)d_in[5];
    const float* g1     = (const float*)d_in[6];
    const float* b1     = (const float*)d_in[7];
    const float* g2     = (const float*)d_in[8];
    const float* b2     = (const float*)d_in[9];
    const float* w1     = (const float*)d_in[10];
    const float* bb1    = (const float*)d_in[11];
    const float* w2     = (const float*)d_in[12];
    const float* bb2    = (const float*)d_in[13];
    float* out = (float*)d_out;

    float *h2;
    bf16 *qkv, *wq, *wp, *w1b, *w2b;
    cudaGetSymbolAddress((void**)&qkv, g_qkv);
    cudaGetSymbolAddress((void**)&h2,  g_h2);
    cudaGetSymbolAddress((void**)&wq,  g_wq);
    cudaGetSymbolAddress((void**)&wp,  g_wp);
    cudaGetSymbolAddress((void**)&w1b, g_w1);
    cudaGetSymbolAddress((void**)&w2b, g_w2);

    cudaFuncSetAttribute(qkv_kernel,      cudaFuncAttributeMaxDynamicSharedMemorySize, 81920);
    cudaFuncSetAttribute(attnproj_kernel, cudaFuncAttributeMaxDynamicSharedMemorySize, 65536);
    cudaFuncSetAttribute(mlp_kernel,      cudaFuncAttributeMaxDynamicSharedMemorySize, 73728);

    wconv_all<<<512, 256>>>(qkv_w, proj_w, w1, w2, wq, wp, w1b, w2b);

    qkv_kernel<<<TOK / 128, 256, 81920>>>(x, g1, b1, wq, qkv_b, qkv);
    attnproj_kernel<<<TOK / 128, 256, 65536>>>(qkv, rpb, wp, proj_b, x, h2);
    mlp_kernel<<<TOK / 64, 256, 73728>>>(h2, g2, b2, w1b, bb1, w2b, bb2, out);
}

// round 15
// speedup vs baseline: 1.0931x; 1.0282x over previous
#include <cuda_runtime.h>
#include <cuda_bf16.h>
#include <math.h>
#include <stdint.h>

// ---------------------------------------------------------------------------
// Swin block: B=32, H=W=128, C=128, WS=2, SS=1, NH=8, HD=16
// R15: all three kernels at 3 CTA/SM (M=64 tiles, MT=2, <=76KB smem, ~80 regs)
// GEMMs: mma.sync plain bf16 1-pass, k32 weight chunks (SW64).
// ---------------------------------------------------------------------------

#define TOK   524288

typedef __nv_bfloat16 bf16;

__device__ bf16  g_qkv[(size_t)TOK * 384];   // bf16 qkv (q pre-scaled)
__device__ float g_h2 [(size_t)TOK * 128];
// weights transposed to [N,K] bf16
__device__ bf16  g_wq[384 * 128];
__device__ bf16  g_wp[128 * 128];
__device__ bf16  g_w1[256 * 128];
__device__ bf16  g_w2[128 * 256];

// ---------------------------------------------------------------------------
__device__ __forceinline__ uint32_t smem_u32(const void* p) {
    uint32_t a;
    asm("{ .reg .u64 t; cvta.to.shared.u64 t, %1; cvt.u32.u64 %0, t; }"
        : "=r"(a) : "l"(p));
    return a;
}

#define SWZ128(o) ((o) ^ (((o) >> 3) & 0x70))
#define SWZ64(o)  ((o) ^ (((o) >> 3) & 0x30))

#define CP_ASYNC16(dst, src) \
    asm volatile("cp.async.cg.shared.global [%0], [%1], 16;" \
                 :: "r"(dst), "l"(src) : "memory")
#define CP_COMMIT()  asm volatile("cp.async.commit_group;" ::: "memory")
#define CP_WAIT0()   asm volatile("cp.async.wait_group 0;" ::: "memory")
#define CP_WAIT1()   asm volatile("cp.async.wait_group 1;" ::: "memory")

__device__ __forceinline__ void ldsm4(uint32_t r[4], uint32_t addr) {
    asm volatile("ldmatrix.sync.aligned.m8n8.x4.shared.b16 {%0,%1,%2,%3}, [%4];"
                 : "=r"(r[0]), "=r"(r[1]), "=r"(r[2]), "=r"(r[3]) : "r"(addr));
}

__device__ __forceinline__ void mma_bf16(float4& d, const uint32_t a[4],
                                         const uint32_t b[2]) {
    asm volatile(
        "mma.sync.aligned.m16n8k16.row.col.f32.bf16.bf16.f32 "
        "{%0,%1,%2,%3}, {%4,%5,%6,%7}, {%8,%9}, {%0,%1,%2,%3};"
        : "+f"(d.x), "+f"(d.y), "+f"(d.z), "+f"(d.w)
        : "r"(a[0]), "r"(a[1]), "r"(a[2]), "r"(a[3]), "r"(b[0]), "r"(b[1]));
}

__device__ __forceinline__ int orig_of(int r) {
    int win = r >> 2, s = r & 3;
    int b  = win >> 12;
    int w  = win & 4095;
    int wh = w >> 6, ww = w & 63;
    int ii = ((wh << 1) + (s >> 1) + 1) & 127;
    int jj = ((ww << 1) + (s & 1) + 1) & 127;
    return (b << 14) + (ii << 7) + jj;
}

__device__ __forceinline__ uint32_t pk2(float a, float b) {
    __nv_bfloat162 t = __floats2bfloat162_rn(a, b);
    return *(uint32_t*)&t;
}
__device__ __forceinline__ float4 ld4bf(const bf16* p) {
    uint2 u = __ldg((const uint2*)p);
    float2 fa = __bfloat1622float2(*(__nv_bfloat162*)&u.x);
    float2 fb = __bfloat1622float2(*(__nv_bfloat162*)&u.y);
    return make_float4(fa.x, fa.y, fb.x, fb.y);
}
// gelu via HW tanh
__device__ __forceinline__ float gelu_t(float x) {
    float u = 0.7978845608f * x * fmaf(0.044715f, x * x, 1.0f);
    float t;
    asm("tanh.approx.f32 %0, %1;" : "=f"(t) : "f"(u));
    return 0.5f * x * (1.0f + t);
}

// ---------------------------------------------------------------------------
// LN of ROWS rows -> plain bf16 SW128 A region at smem offset 0.
// ---------------------------------------------------------------------------
template <bool GATHER, int ROWS>
__device__ __forceinline__ void ln_to_smem(
    const float* __restrict__ in, const float* __restrict__ gamma,
    const float* __restrict__ beta, char* smem, int rowBase)
{
    const int tid = threadIdx.x, lane = tid & 31, wid = tid >> 5;
    const float4 g = *(const float4*)(gamma + lane * 4);
    const float4 b = *(const float4*)(beta  + lane * 4);
    const uint32_t colOff = (uint32_t)((lane & 15) * 8);
    char* dhi = smem + (lane >> 4) * (ROWS * 128);
#pragma unroll 4
    for (int r = wid; r < ROWS; r += 8) {
        int src = GATHER ? orig_of(rowBase + r) : (rowBase + r);
        float4 v = __ldg((const float4*)(in + (size_t)src * 128 + lane * 4));
        float s = v.x + v.y + v.z + v.w;
        float q = v.x * v.x + v.y * v.y + v.z * v.z + v.w * v.w;
#pragma unroll
        for (int o = 16; o; o >>= 1) {
            s += __shfl_xor_sync(0xffffffffu, s, o);
            q += __shfl_xor_sync(0xffffffffu, q, o);
        }
        float mean = s * (1.0f / 128.0f);
        float rstd = rsqrtf(q * (1.0f / 128.0f) - mean * mean + 1e-5f);
        float o0 = (v.x - mean) * rstd * g.x + b.x;
        float o1 = (v.y - mean) * rstd * g.y + b.y;
        float o2 = (v.z - mean) * rstd * g.z + b.z;
        float o3 = (v.w - mean) * rstd * g.w + b.w;
        uint32_t o16 = SWZ128((uint32_t)(r * 128) + colOff);
        *(uint2*)(dhi + o16) = make_uint2(pk2(o0, o1), pk2(o2, o3));
    }
}

// ---------------------------------------------------------------------------
// cp.async one 128(N) x 32(k) bf16 weight chunk -> 8KB SW64 region.
// ---------------------------------------------------------------------------
__device__ __forceinline__ void load_wk32(
    uint32_t dst, const bf16* __restrict__ w,
    int rowOff, int kOff, int kStride)
{
    const int tid = threadIdx.x, c16 = tid & 3;
#pragma unroll
    for (int it = 0; it < 2; it++) {
        int row = (tid >> 2) + it * 64;
        uint32_t d = dst + SWZ64((uint32_t)(row * 64 + c16 * 16));
        CP_ASYNC16(d, w + (size_t)(rowOff + row) * kStride + kOff + c16 * 8);
    }
    CP_COMMIT();
}

// ---------------------------------------------------------------------------
// k32 half-chunk warp MMA (A SW128 k64 region, khalf picks k-half;
// B 8KB SW64 k32 chunk).
// ---------------------------------------------------------------------------
template <int MT>
__device__ __forceinline__ void mma_k32(
    float4 (&acc)[MT][4], uint32_t aBase, int khalf, uint32_t bBase)
{
    const int lane = threadIdx.x & 31, wid = threadIdx.x >> 5;
    const int warp_m = wid >> 2, warp_n = wid & 3;
    const int arow = warp_m * (MT * 16) + (lane & 15);
    const int akb  = (lane >> 4) * 8;
    const int brow = warp_n * 32 + ((lane >> 4) & 1) * 8 + (lane & 7);
    const int bkb  = ((lane >> 3) & 1) * 8;
#pragma unroll
    for (int ks = 0; ks < 2; ks++) {
        const int kA = (khalf * 32 + ks * 16 + akb) * 2;
        const int kB = (ks * 16 + bkb) * 2;
        uint32_t bh[2][4];
#pragma unroll
        for (int i = 0; i < 2; i++) {
            uint32_t boff = SWZ64((uint32_t)((brow + i * 16) * 64 + kB));
            ldsm4(bh[i], bBase + boff);
        }
#pragma unroll
        for (int mt = 0; mt < MT; mt++) {
            uint32_t aoff = SWZ128((uint32_t)((arow + mt * 16) * 128 + kA));
            uint32_t ah[4];
            ldsm4(ah, aBase + aoff);
#pragma unroll
            for (int nt = 0; nt < 4; nt++)
                mma_bf16(acc[mt][nt], ah, &bh[nt >> 1][(nt & 1) * 2]);
        }
    }
}

// ---------------------------------------------------------------------------
// Weight transpose: w[K,N] fp32 -> [N,K] bf16 (all 4 weights, one launch)
// ---------------------------------------------------------------------------
__global__ void wconv_all(
    const float* __restrict__ qkv_w, const float* __restrict__ proj_w,
    const float* __restrict__ w1, const float* __restrict__ w2,
    bf16* wq, bf16* wp, bf16* w1b, bf16* w2b)
{
    int idx = blockIdx.x * 256 + threadIdx.x;   // 131072 total
    const float* w; bf16* o; int K, N;
    if (idx < 49152)       { w = qkv_w;  o = wq;  K = 128; N = 384; }
    else if (idx < 65536)  { idx -= 49152; w = proj_w; o = wp;  K = 128; N = 128; }
    else if (idx < 98304)  { idx -= 65536; w = w1; o = w1b; K = 128; N = 256; }
    else                   { idx -= 98304; w = w2; o = w2b; K = 256; N = 128; }
    int n = idx / K, k = idx - n * K;
    o[idx] = __float2bfloat16(w[(size_t)k * N + n]);
}

// ---------------------------------------------------------------------------
// Kernel 1: LN1(+gather) + qkv GEMM -> bf16 qkv.  M=64, MT=2, 3 CTA/SM.
// smem: A 16KB @0 | W 3x8KB @16384 -> 40960.  12 k32 chunks.
// ---------------------------------------------------------------------------
__global__ __launch_bounds__(256, 3) void qkv_kernel(
    const float* __restrict__ x, const float* __restrict__ g1,
    const float* __restrict__ b1, const bf16* __restrict__ wq,
    const float* __restrict__ qkv_b, bf16* __restrict__ qkv)
{
    extern __shared__ char smem[];
    const uint32_t sb = smem_u32(smem);
    const int tid = threadIdx.x, lane = tid & 31, wid = tid >> 5;
    const int warp_m = wid >> 2, warp_n = wid & 3;
    const int rowBase = blockIdx.x << 6;   // 64 rows
    const int r4 = lane >> 2, c2 = (lane & 3) * 2;

    auto issueW = [&](int c) {
        load_wk32(sb + 16384 + (c % 3) * 8192, wq,
                  (c >> 2) * 128, (c & 3) * 32, 128);
    };

    issueW(0);
    ln_to_smem<true, 64>(x, g1, b1, smem, rowBase);
    issueW(1);

#pragma unroll
    for (int p = 0; p < 3; p++) {
        float4 acc[2][4];
#pragma unroll
        for (int a = 0; a < 2; a++)
#pragma unroll
            for (int j = 0; j < 4; j++) acc[a][j] = make_float4(0, 0, 0, 0);
#pragma unroll
        for (int h = 0; h < 4; h++) {
            const int c = p * 4 + h;
            if (c == 11) CP_WAIT0(); else CP_WAIT1();
            __syncthreads();
            mma_k32<2>(acc, sb + (h >> 1) * 8192, h & 1,
                       sb + 16384 + (c % 3) * 8192);
            if (c + 2 <= 11) issueW(c + 2);
        }
        const float scale = (p == 0) ? 0.25f : 1.0f;
#pragma unroll
        for (int mt = 0; mt < 2; mt++)
#pragma unroll
            for (int half = 0; half < 2; half++) {
                const int gr = rowBase + warp_m * 32 + mt * 16 + r4 + half * 8;
#pragma unroll
                for (int nt = 0; nt < 4; nt++) {
                    const int col = p * 128 + warp_n * 32 + nt * 8 + c2;
                    float v0 = half ? acc[mt][nt].z : acc[mt][nt].x;
                    float v1 = half ? acc[mt][nt].w : acc[mt][nt].y;
                    v0 = (v0 + __ldg(qkv_b + col)) * scale;
                    v1 = (v1 + __ldg(qkv_b + col + 1)) * scale;
                    *(uint32_t*)(qkv + (size_t)gr * 384 + col) = pk2(v0, v1);
                }
            }
    }
}

// ---------------------------------------------------------------------------
// Kernel 2: window attention + proj GEMM + residual.  M=64, MT=2, 3 CTA/SM.
// smem: O 16KB @0 | W 4x8KB static @16384 -> 49152.  1 wait + 1 barrier.
// ---------------------------------------------------------------------------
__global__ __launch_bounds__(256, 3) void attnproj_kernel(
    const bf16* __restrict__ qkv, const float* __restrict__ rpb,
    const bf16* __restrict__ wp, const float* __restrict__ proj_b,
    const float* __restrict__ x, float* __restrict__ h2)
{
    extern __shared__ char smem[];
    const uint32_t sb = smem_u32(smem);
    const int tid = threadIdx.x, lane = tid & 31, wid = tid >> 5;
    const int warp_m = wid >> 2, warp_n = wid & 3;
    const int rowBase = blockIdx.x << 6;
    const int win0    = blockIdx.x << 4;   // 16 windows per CTA
    const int h = lane >> 2, i = lane & 3;
    const int dy1 = i >> 1, dx1 = i & 1;

    // all 4 proj W k32 chunks up front (hidden under attention)
#pragma unroll
    for (int c = 0; c < 4; c++)
        load_wk32(sb + 16384 + c * 8192, wp, 0, c * 32, 128);

    // ---- attention: each warp handles 2 windows ----------------------------
#pragma unroll
    for (int t = 0; t < 2; t++) {
        const int wl  = wid * 2 + t;
        const int win = win0 + wl;
        const int w   = win & 4095;
        const bool mr = ((w >> 6) == 63);
        const bool mc = ((w & 63) == 63);
        const bf16* base = qkv + (size_t)win * (4 * 384);

        float q[16];
        const bf16* qp = base + i * 384 + h * 16;
#pragma unroll
        for (int d4 = 0; d4 < 4; d4++) {
            float4 v = ld4bf(qp + d4 * 4);
            q[d4 * 4 + 0] = v.x; q[d4 * 4 + 1] = v.y;
            q[d4 * 4 + 2] = v.z; q[d4 * 4 + 3] = v.w;
        }
        float s[4];
#pragma unroll
        for (int j = 0; j < 4; j++) {
            const bf16* kp = base + j * 384 + 128 + h * 16;
            float a = 0.0f;
#pragma unroll
            for (int d4 = 0; d4 < 4; d4++) {
                float4 v = ld4bf(kp + d4 * 4);
                a += q[d4 * 4 + 0] * v.x + q[d4 * 4 + 1] * v.y
                   + q[d4 * 4 + 2] * v.z + q[d4 * 4 + 3] * v.w;
            }
            int dy2 = j >> 1, dx2 = j & 1;
            bool ok = (!mr || dy1 == dy2) && (!mc || dx1 == dx2);
            s[j] = a + __ldg(rpb + ((dy1 - dy2 + 1) * 3 + (dx1 - dx2 + 1)) * 8 + h)
                 + (ok ? 0.0f : -100.0f);
        }
        float mx = fmaxf(fmaxf(s[0], s[1]), fmaxf(s[2], s[3]));
        float p[4], sum = 0.0f;
#pragma unroll
        for (int j = 0; j < 4; j++) { p[j] = expf(s[j] - mx); sum += p[j]; }
        float inv = 1.0f / sum;

        float ov[16];
#pragma unroll
        for (int d = 0; d < 16; d++) ov[d] = 0.0f;
#pragma unroll
        for (int j = 0; j < 4; j++) {
            const bf16* vp = base + j * 384 + 256 + h * 16;
            float pj = p[j] * inv;
#pragma unroll
            for (int d4 = 0; d4 < 4; d4++) {
                float4 v = ld4bf(vp + d4 * 4);
                ov[d4 * 4 + 0] += pj * v.x; ov[d4 * 4 + 1] += pj * v.y;
                ov[d4 * 4 + 2] += pj * v.z; ov[d4 * 4 + 3] += pj * v.w;
            }
        }
        // store O into A region (SW128, ROWS=64 layout: 2 k64 chunks of 8KB)
        const int row = wl * 4 + i;
#pragma unroll
        for (int d4 = 0; d4 < 4; d4++) {
            const int ch = h * 16 + d4 * 4;
            char* dst = smem + (ch >> 6) * 8192;
            uint32_t o16 = SWZ128((uint32_t)(row * 128 + (ch & 63) * 2));
            *(uint2*)(dst + o16) = make_uint2(pk2(ov[d4 * 4], ov[d4 * 4 + 1]),
                                              pk2(ov[d4 * 4 + 2], ov[d4 * 4 + 3]));
        }
    }

    // ---- proj GEMM: single wait + barrier, 4 k32 chunks ---------------------
    float4 acc[2][4];
#pragma unroll
    for (int a = 0; a < 2; a++)
#pragma unroll
        for (int j = 0; j < 4; j++) acc[a][j] = make_float4(0, 0, 0, 0);

    CP_WAIT0();
    __syncthreads();
#pragma unroll
    for (int c = 0; c < 4; c++)
        mma_k32<2>(acc, sb + (c >> 1) * 8192, c & 1, sb + 16384 + c * 8192);

    const int r4 = lane >> 2, c2 = (lane & 3) * 2;
#pragma unroll
    for (int mt = 0; mt < 2; mt++)
#pragma unroll
        for (int half = 0; half < 2; half++) {
            const int gr = rowBase + warp_m * 32 + mt * 16 + r4 + half * 8;
            const size_t outRow = (size_t)orig_of(gr);
#pragma unroll
            for (int nt = 0; nt < 4; nt++) {
                const int col = warp_n * 32 + nt * 8 + c2;
                float v0 = half ? acc[mt][nt].z : acc[mt][nt].x;
                float v1 = half ? acc[mt][nt].w : acc[mt][nt].y;
                const float2 sk = *(const float2*)(x + outRow * 128 + col);
                v0 += __ldg(proj_b + col) + sk.x;
                v1 += __ldg(proj_b + col + 1) + sk.y;
                *(float2*)(h2 + outRow * 128 + col) = make_float2(v0, v1);
            }
        }
}

// ---------------------------------------------------------------------------
// Kernel 3: LN2 + MLP1(GELU) + MLP2 + residual.  M=64, MT=2, 3 CTA/SM.  (R14)
// smem: L2A 16KB @0 | M1 32KB @16384 | W 3x8KB @49152 -> 73728.  16 chunks.
// ---------------------------------------------------------------------------
__global__ __launch_bounds__(256, 3) void mlp_kernel(
    const float* __restrict__ h2, const float* __restrict__ g2,
    const float* __restrict__ b2,
    const bf16* __restrict__ w1, const float* __restrict__ bb1,
    const bf16* __restrict__ w2, const float* __restrict__ bb2,
    float* __restrict__ out)
{
    extern __shared__ char smem[];
    const uint32_t sb = smem_u32(smem);
    const int tid = threadIdx.x, lane = tid & 31, wid = tid >> 5;
    const int warp_m = wid >> 2, warp_n = wid & 3;
    const int rowBase = blockIdx.x << 6;
    const int r4 = lane >> 2, c2 = (lane & 3) * 2;

    auto issueW = [&](int c) {
        const uint32_t dst = sb + 49152 + (c % 3) * 8192;
        if (c < 8) load_wk32(dst, w1, (c >> 2) * 128, (c & 3) * 32, 128);
        else       load_wk32(dst, w2, 0, (c - 8) * 32, 256);
    };

    issueW(0);
    ln_to_smem<false, 64>(h2, g2, b2, smem, rowBase);
    issueW(1);

    // ---- mlp1: 2 N-passes x 4 k32 chunks; gelu -> M1 ------------------------
#pragma unroll
    for (int pass = 0; pass < 2; pass++) {
        float4 acc1[2][4];
#pragma unroll
        for (int a = 0; a < 2; a++)
#pragma unroll
            for (int j = 0; j < 4; j++) acc1[a][j] = make_float4(0, 0, 0, 0);
#pragma unroll
        for (int h = 0; h < 4; h++) {
            const int c = pass * 4 + h;
            CP_WAIT1();
            __syncthreads();
            mma_k32<2>(acc1, sb + (h >> 1) * 8192, h & 1,
                       sb + 49152 + (c % 3) * 8192);
            issueW(c + 2);
        }
#pragma unroll
        for (int mt = 0; mt < 2; mt++)
#pragma unroll
            for (int half = 0; half < 2; half++) {
                const int row = warp_m * 32 + mt * 16 + r4 + half * 8;
#pragma unroll
                for (int nt = 0; nt < 4; nt++) {
                    const int ch = warp_n * 32 + nt * 8 + c2;
                    float v0 = half ? acc1[mt][nt].z : acc1[mt][nt].x;
                    float v1 = half ? acc1[mt][nt].w : acc1[mt][nt].y;
                    v0 = gelu_t(v0 + __ldg(bb1 + pass * 128 + ch));
                    v1 = gelu_t(v1 + __ldg(bb1 + pass * 128 + ch + 1));
                    char* dst = smem + 16384 + (pass * 2 + (ch >> 6)) * 8192;
                    uint32_t o16 = SWZ128((uint32_t)(row * 128 + (ch & 63) * 2));
                    *(uint32_t*)(dst + o16) = pk2(v0, v1);
                }
            }
    }

    // ---- mlp2: K=256 as 8 k32 chunks over M1 --------------------------------
    float4 acc2[2][4];
#pragma unroll
    for (int a = 0; a < 2; a++)
#pragma unroll
        for (int j = 0; j < 4; j++) acc2[a][j] = make_float4(0, 0, 0, 0);

#pragma unroll
    for (int j = 0; j < 8; j++) {
        const int c = 8 + j;
        if (c == 15) CP_WAIT0(); else CP_WAIT1();
        __syncthreads();
        mma_k32<2>(acc2, sb + 16384 + (j >> 1) * 8192, j & 1,
                   sb + 49152 + (c % 3) * 8192);
        if (c + 2 <= 15) issueW(c + 2);
    }

    // ---- epilogue: out = acc2 + b2 + h2 -------------------------------------
#pragma unroll
    for (int mt = 0; mt < 2; mt++)
#pragma unroll
        for (int half = 0; half < 2; half++) {
            const int gr = rowBase + warp_m * 32 + mt * 16 + r4 + half * 8;
#pragma unroll
            for (int nt = 0; nt < 4; nt++) {
                const int col = warp_n * 32 + nt * 8 + c2;
                float v0 = half ? acc2[mt][nt].z : acc2[mt][nt].x;
                float v1 = half ? acc2[mt][nt].w : acc2[mt][nt].y;
                const float2 sk = *(const float2*)(h2 + (size_t)gr * 128 + col);
                v0 += __ldg(bb2 + col) + sk.x;
                v1 += __ldg(bb2 + col + 1) + sk.y;
                *(float2*)(out + (size_t)gr * 128 + col) = make_float2(v0, v1);
            }
        }
}

// ---------------------------------------------------------------------------
extern "C" void kernel_launch(void* const* d_in, const int* in_sizes, int n_in,
                              void* d_out, int out_size)
{
    const float* x      = (const float*)d_in[0];
    const float* qkv_w  = (const float*)d_in[1];
    const float* qkv_b  = (const float*)d_in[2];
    const float* proj_w = (const float*)d_in[3];
    const float* proj_b = (const float*)d_in[4];
    const float* rpb    = (const float*)d_in[5];
    const float* g1     = (const float*)d_in[6];
    const float* b1     = (const float*)d_in[7];
    const float* g2     = (const float*)d_in[8];
    const float* b2     = (const float*)d_in[9];
    const float* w1     = (const float*)d_in[10];
    const float* bb1    = (const float*)d_in[11];
    const float* w2     = (const float*)d_in[12];
    const float* bb2    = (const float*)d_in[13];
    float* out = (float*)d_out;

    float *h2;
    bf16 *qkv, *wq, *wp, *w1b, *w2b;
    cudaGetSymbolAddress((void**)&qkv, g_qkv);
    cudaGetSymbolAddress((void**)&h2,  g_h2);
    cudaGetSymbolAddress((void**)&wq,  g_wq);
    cudaGetSymbolAddress((void**)&wp,  g_wp);
    cudaGetSymbolAddress((void**)&w1b, g_w1);
    cudaGetSymbolAddress((void**)&w2b, g_w2);

    cudaFuncSetAttribute(qkv_kernel,      cudaFuncAttributeMaxDynamicSharedMemorySize, 40960);
    cudaFuncSetAttribute(attnproj_kernel, cudaFuncAttributeMaxDynamicSharedMemorySize, 49152);
    cudaFuncSetAttribute(mlp_kernel,      cudaFuncAttributeMaxDynamicSharedMemorySize, 73728);

    wconv_all<<<512, 256>>>(qkv_w, proj_w, w1, w2, wq, wp, w1b, w2b);

    qkv_kernel<<<TOK / 64, 256, 40960>>>(x, g1, b1, wq, qkv_b, qkv);
    attnproj_kernel<<<TOK / 64, 256, 49152>>>(qkv, rpb, wp, proj_b, x, h2);
    mlp_kernel<<<TOK / 64, 256, 73728>>>(h2, g2, b2, w1b, bb1, w2b, bb2, out);
}